// round 12
// baseline (speedup 1.0000x reference)
#include <cuda_runtime.h>
#include <math.h>
#include <stdint.h>
#include <string.h>

#define BB 32
#define TT 1024
#define II 512
#define HH 1024
#define GCTA 128
#define NT 512
#define QS 32512.0f                      // 15-bit digit scale (127*256)
#define WSC (256.0f / (32512.0f * 32512.0f))

typedef unsigned long long ull;

// ---------------- device global scratch ----------------
__device__ float  g_xT[(size_t)TT * II * BB];          // x transposed [t][i][b]
__device__ float4 g_wpx[(size_t)128 * 256 * 8];        // x-proj weights pair-packed
__device__ ull    g_gx[(size_t)TT * HH * BB];          // precomputed x-gates (z,h~) fp32 pair
__device__ float  g_wscale[4096];                      // per-(gate,j) row max
__device__ unsigned g_wfrag[(size_t)GCTA * 24576];     // per-CTA int8 weight frag images
__device__ unsigned g_bimgN[(size_t)(TT + 1) * 32768]; // per-step int8 act frag images (134MB)
__device__ volatile int g_flags[GCTA];

// ---------------- helpers ----------------
__device__ __forceinline__ ull dup2(float w) {
    ull r; asm("mov.b64 %0, {%1, %1};" : "=l"(r) : "f"(w)); return r;
}
__device__ __forceinline__ void ffma2(ull &d, ull a, ull b) {
    asm("fma.rn.f32x2 %0, %1, %2, %0;" : "+l"(d) : "l"(a), "l"(b));
}
__device__ __forceinline__ ull add2(ull a, ull b) {
    ull d; asm("add.rn.f32x2 %0, %1, %2;" : "=l"(d) : "l"(a), "l"(b)); return d;
}
__device__ __forceinline__ void unpack2(ull v, float &lo, float &hi) {
    asm("mov.b64 {%0, %1}, %2;" : "=f"(lo), "=f"(hi) : "l"(v));
}
__device__ __forceinline__ void stcg32(unsigned* p, unsigned v) {
    asm volatile("st.global.cg.u32 [%0], %1;" :: "l"(p), "r"(v) : "memory");
}
__device__ __forceinline__ void mma_s8(int* d, uint4 a, uint2 b) {
    asm volatile(
        "mma.sync.aligned.m16n8k32.row.col.s32.s8.s8.s32 "
        "{%0,%1,%2,%3}, {%4,%5,%6,%7}, {%8,%9}, {%0,%1,%2,%3};"
        : "+r"(d[0]), "+r"(d[1]), "+r"(d[2]), "+r"(d[3])
        : "r"(a.x), "r"(a.y), "r"(a.z), "r"(a.w), "r"(b.x), "r"(b.y));
}
// quantize v in (-1,1)*s -> 15-bit digit pair
__device__ __forceinline__ void quant15(float v, float inv, int &hi, int &lo) {
    int q = __float2int_rn(v * inv);
    q = min(32512, max(-32512, q));
    hi = (q + 128) >> 8;
    lo = q - (hi << 8);
}

// ---------------- flag-based grid barrier ----------------
__device__ __forceinline__ void gridbar(int target, int cta, int tid) {
    __syncthreads();
    if (tid == 0) { __threadfence(); g_flags[cta] = target; }
    if (tid < 32) {
        bool done = false;
        while (!done) {
            int ok = 1;
#pragma unroll
            for (int q = 0; q < GCTA / 32; q++)
                if (g_flags[tid + 32 * q] < target) ok = 0;
            done = __all_sync(0xffffffffu, ok);
        }
        __threadfence();
    }
    __syncthreads();
}

// ---------------- prep1: transpose x + pack x-proj weights + row scales --------
__global__ void k_prep1(const float* __restrict__ x,
                        const float* __restrict__ W_z0, const float* __restrict__ W_in0,
                        const float* __restrict__ U_z0, const float* __restrict__ W_res0,
                        const float* __restrict__ W_z1, const float* __restrict__ U_z1,
                        const float* __restrict__ W_in1, const float* __restrict__ W_res1) {
    int bid = blockIdx.x;
    if (bid < 16384) {
        __shared__ float tile[32][33];
        int t = bid >> 4;
        int i0 = (bid & 15) * 32;
        int lane = threadIdx.x & 31, row = threadIdx.x >> 5;
#pragma unroll
        for (int r = 0; r < 4; r++) {
            int b = row * 4 + r;
            tile[b][lane] = x[((size_t)b * TT + t) * II + i0 + lane];
        }
        __syncthreads();
#pragma unroll
        for (int r = 0; r < 4; r++) {
            int ii = row * 4 + r;
            g_xT[((size_t)t * II + i0 + ii) * BB + lane] = tile[lane][ii];
        }
    } else if (bid < 17408) {
        int idx = (bid - 16384) * 256 + threadIdx.x;
        if (idx < 128 * 256 * 8) {
            int j  = idx & 7;
            int r  = idx >> 3;
            int k2 = r & 255;
            int jb = r >> 8;
            size_t row = (size_t)(jb * 8 + j) * II;
            float4 v;
            v.x = W_z0[row + 2 * k2];     v.y = W_in0[row + 2 * k2];
            v.z = W_z0[row + 2 * k2 + 1]; v.w = W_in0[row + 2 * k2 + 1];
            g_wpx[idx] = v;
        }
    } else {
        // per-(gate, j) row-max scale
        __shared__ float smax[256];
        int rowid = bid - 17408;           // 0..4095
        int gate = rowid >> 10, j = rowid & 1023;
        const float *pA = 0, *pB = 0;
        if (gate == 0)      { pA = U_z0 + (size_t)j * HH; }
        else if (gate == 1) { pA = W_res0 + (size_t)j * HH; }
        else if (gate == 2) { pA = W_z1 + (size_t)j * HH; pB = U_z1 + (size_t)j * HH; }
        else                { pA = W_in1 + (size_t)j * HH; pB = W_res1 + (size_t)j * HH; }
        float m = 0.f;
        for (int k = threadIdx.x; k < HH; k += 256) {
            m = fmaxf(m, fabsf(pA[k]));
            if (pB) m = fmaxf(m, fabsf(pB[k]));
        }
        smax[threadIdx.x] = m;
        __syncthreads();
        for (int s = 128; s > 0; s >>= 1) {
            if (threadIdx.x < s) smax[threadIdx.x] = fmaxf(smax[threadIdx.x], smax[threadIdx.x + s]);
            __syncthreads();
        }
        if (threadIdx.x == 0) g_wscale[rowid] = fmaxf(smax[0], 1e-30f);
    }
}

// ---------------- gx: precompute x-gates (fp32 exact) ----------------
__global__ void __launch_bounds__(256, 1) k_gx(const float* __restrict__ dummy) {
    extern __shared__ ull sm_gx[];
    ulonglong2* sw = (ulonglong2*)sm_gx;
    ull*        pr = sm_gx + 4096;

    const int jb = blockIdx.x;
    const int tb = blockIdx.y;
    const int tid = threadIdx.x;
    const int w = tid >> 5;
    const int lane = tid & 31;

    const float4* src = g_wpx + (size_t)jb * 2048;
#pragma unroll
    for (int u = 0; u < 8; u++) ((float4*)sw)[tid + u * 256] = src[tid + u * 256];
    __syncthreads();

    for (int tt = 0; tt < 8; tt++) {
        const int t = tb * 8 + tt;
        ull acc[8];
#pragma unroll
        for (int j = 0; j < 8; j++) acc[j] = 0;
        const float* xp = g_xT + (size_t)t * II * BB;
#pragma unroll 4
        for (int u = 0; u < 32; u++) {
            const int k2 = w * 32 + u;
            ull A0 = dup2(__ldg(xp + (2 * k2) * BB + lane));
            ull A1 = dup2(__ldg(xp + (2 * k2 + 1) * BB + lane));
#pragma unroll
            for (int j = 0; j < 8; j++) {
                ulonglong2 wv = sw[k2 * 8 + j];
                ffma2(acc[j], wv.x, A0);
                ffma2(acc[j], wv.y, A1);
            }
        }
#pragma unroll
        for (int j = 0; j < 8; j++) pr[w * 256 + j * 32 + lane] = acc[j];
        __syncthreads();
        if (tid < 256) {
            const int e_j = tid >> 5;
            const int e_b = tid & 31;
            ull s = pr[e_j * 32 + e_b];
#pragma unroll
            for (int ww = 1; ww < 8; ww++) s = add2(s, pr[ww * 256 + e_j * 32 + e_b]);
            g_gx[((size_t)t * HH + jb * 8 + e_j) * BB + e_b] = s;
        }
        __syncthreads();
    }
}

// ---------------- prep2: pack int8 weight frag images + seed act images ---------
// Per CTA (words): [mt0_hi 4096][mt0_lo 4096][mt1_hi 8192][mt1_lo 8192]
// A frag s8 m16n8k32 row-major: lane(g=l>>2,tg=l&3), reg r: row=g+8*(r&1),
//   k = kstep*32 + 4*tg + 16*(r>>1) + byte
__global__ void k_prep2(const float* __restrict__ U_z0, const float* __restrict__ W_res0,
                        const float* __restrict__ W_z1, const float* __restrict__ U_z1,
                        const float* __restrict__ W_in1, const float* __restrict__ W_res1,
                        const float* __restrict__ h0)
{
    int bid = blockIdx.x;
    if (bid < 12288) {
        size_t idx = (size_t)bid * 256 + threadIdx.x;
        int cta = (int)(idx / 24576);
        int rem = (int)(idx % 24576);
        int mt, digit, wsub;
        if (rem < 4096)       { mt = 0; digit = 0; wsub = rem; }
        else if (rem < 8192)  { mt = 0; digit = 1; wsub = rem - 4096; }
        else if (rem < 16384) { mt = 1; digit = 0; wsub = rem - 8192; }
        else                  { mt = 1; digit = 1; wsub = rem - 16384; }
        int r = wsub & 3;
        int lane = (wsub >> 2) & 31;
        int kstep = wsub >> 7;
        int g = lane >> 2, tg = lane & 3;
        int row = g + 8 * (r & 1);
        int kbase = kstep * 32 + 4 * tg + 16 * (r >> 1);
        int j = cta * 8 + (row & 7);
        int gate = mt * 2 + (row >> 3);
        float inv = QS / g_wscale[gate * 1024 + j];
        unsigned word = 0;
#pragma unroll
        for (int byte = 0; byte < 4; byte++) {
            int k = kbase + byte;
            float v;
            if (mt == 0) {
                v = (row < 8) ? U_z0[(size_t)j * HH + k] : W_res0[(size_t)j * HH + k];
            } else {
                if (row < 8) v = (k < 1024) ? W_z1[(size_t)j * HH + k] : U_z1[(size_t)j * HH + k - 1024];
                else         v = (k < 1024) ? W_in1[(size_t)j * HH + k] : W_res1[(size_t)j * HH + k - 1024];
            }
            int hi, lo; quant15(v, inv, hi, lo);
            int sel = digit ? lo : hi;
            word |= ((unsigned)(sel & 0xff)) << (8 * byte);
        }
        g_wfrag[idx] = word;
    } else {
        if (bid == 12288 && threadIdx.x < GCTA) g_flags[threadIdx.x] = 0;
        int idx = (bid - 12288) * 256 + threadIdx.x;   // over 2048*32
        if (idx < 2048 * 32) {
            int k = idx >> 5, b = idx & 31;
            float v = (k < 1024) ? h0[(size_t)(0 * BB + b) * HH + k]
                                 : h0[(size_t)(1 * BB + b) * HH + (k - 1024)];
            int hi, lo; quant15(v, QS, hi, lo);
            int kstep = k >> 5, koff = k & 31;
            int r = (koff >> 4) & 1, tg = (koff >> 2) & 3, byte = koff & 3;
            int lane = 4 * (b & 7) + tg, nt = b >> 3;
            // word = group*4 + digit*2 + r   (uint4 per lane: x=hiR0,y=hiR1,z=loR0,w=loR1)
            size_t wbase = (((size_t)kstep * 4 + nt) * 32 + lane) * 4;
            unsigned char* p0 = (unsigned char*)g_bimgN;
            p0[(wbase + 0 * 2 + r) * 4 + byte] = (unsigned char)(hi & 0xff);
            p0[(wbase + 1 * 2 + r) * 4 + byte] = (unsigned char)(lo & 0xff);
            if (k >= 1024) {   // buffer 1 needs h1(0) half
                unsigned char* p1 = p0 + (size_t)32768 * 4;
                p1[(wbase + 0 * 2 + r) * 4 + byte] = (unsigned char)(hi & 0xff);
                p1[(wbase + 1 * 2 + r) * 4 + byte] = (unsigned char)(lo & 0xff);
            }
        }
    }
}

// ---------------- main persistent kernel ----------------
// SMEM words: [weights 24576][s_red 8192][s_h0 264][s_h1 264]
#define SMEM_BYTES 133184
__global__ void __launch_bounds__(NT, 1) k_esgp(
    const float* __restrict__ b_z0, const float* __restrict__ b_z1,
    const float* __restrict__ h0in, float* __restrict__ out)
{
    extern __shared__ unsigned smw[];
    const int tid = threadIdx.x, wid = tid >> 5, lane = tid & 31, c = blockIdx.x;

    // preload int8 weight fragment images (96KB)
    {
        const uint4* src = (const uint4*)(g_wfrag + (size_t)c * 24576);
        uint4* dst = (uint4*)smw;
        for (int i = tid; i < 6144; i += NT) dst[i] = src[i];
    }
    float*  s_red  = (float*)(smw + 24576);          // 8192 floats
    float4* s_red4 = (float4*)s_red;
    float*  s_h0   = (float*)(smw + 32768);          // 264 floats
    float*  s_h1   = s_h0 + 264;                     // 264 floats
    __syncthreads();

    // warp role: 8 ksg-slices x 2 nt-halves; each warp covers BOTH M-tiles
    const int ss = wid & 7, nh = wid >> 3;
    const int nt0 = nh * 2, nt1 = nh * 2 + 1;
    const uint4* ws0h = (const uint4*)smw + 0    + lane;   // mt0 hi (1024 uint4)
    const uint4* ws0l = (const uint4*)smw + 1024 + lane;   // mt0 lo
    const uint4* ws1h = (const uint4*)smw + 2048 + lane;   // mt1 hi (2048 uint4)
    const uint4* ws1l = (const uint4*)smw + 4096 + lane;   // mt1 lo

    // epilogue identity (tid<256): thread owns (e_j, e_b)
    const int e_j = wid, e_b = lane;
    const int jg = c * 8 + (e_j & 7);
    float bz0e = 0.f, bz1e = 0.f, h0_old = 0.f, h1_old = 0.f;
    float wsc0 = 0.f, wsc1 = 0.f, wsc2 = 0.f, wsc3 = 0.f;
    if (tid < 256) {
        bz0e = b_z0[jg]; bz1e = b_z1[jg];
        h0_old = h0in[(size_t)(0 * BB + e_b) * HH + jg];
        h1_old = h0in[(size_t)(1 * BB + e_b) * HH + jg];
        wsc0 = g_wscale[0 * 1024 + jg] * WSC;
        wsc1 = g_wscale[1 * 1024 + jg] * WSC;
        wsc2 = g_wscale[2 * 1024 + jg] * WSC;
        wsc3 = g_wscale[3 * 1024 + jg] * WSC;
    }
    // epilogue gather constants
    const int nh_ = e_b >> 4, ntl_ = (e_b >> 3) & 1, col8 = e_b & 7;
    const int tg_ = col8 >> 1, cbit = col8 & 1;
    const int ln = 4 * (e_j & 7) + tg_;

    for (int p = 0; p <= TT; p++) {
        // deferred output write for step p-2 (s_h1 = h1(p-1), stable during MMA)
        if (p >= 2 && tid < 256) {
            int b = tid >> 3, j = tid & 7;
            out[((size_t)b * TT + (p - 2)) * HH + c * 8 + j] = s_h1[j * 33 + b];
        }

        int A0h[4] = {0,0,0,0}, A0m[4] = {0,0,0,0}, B0h[4] = {0,0,0,0}, B0m[4] = {0,0,0,0};
        int A1h[4] = {0,0,0,0}, A1m[4] = {0,0,0,0}, B1h[4] = {0,0,0,0}, B1m[4] = {0,0,0,0};
        const uint4* bi4 = (const uint4*)g_bimgN + (size_t)p * 8192 + lane;

        ull gxv = 0;
        if (tid < 256 && p < TT) gxv = __ldg(&g_gx[((size_t)p * HH + jg) * BB + e_b]);

#pragma unroll 2
        for (int i = 0; i < 8; i++) {
            const int ksg = ss + 8 * i;
            uint4 b0 = __ldg(bi4 + (ksg * 4 + nt0) * 32);
            uint4 b1 = __ldg(bi4 + (ksg * 4 + nt1) * 32);
            uint2 bh0 = make_uint2(b0.x, b0.y), bl0 = make_uint2(b0.z, b0.w);
            uint2 bh1 = make_uint2(b1.x, b1.y), bl1 = make_uint2(b1.z, b1.w);
            uint4 a1h = ws1h[ksg * 32], a1l = ws1l[ksg * 32];
            mma_s8(A1h, a1h, bh0); mma_s8(A1m, a1h, bl0); mma_s8(A1m, a1l, bh0);
            mma_s8(B1h, a1h, bh1); mma_s8(B1m, a1h, bl1); mma_s8(B1m, a1l, bh1);
            if (i < 4) {
                uint4 a0h = ws0h[ksg * 32], a0l = ws0l[ksg * 32];
                mma_s8(A0h, a0h, bh0); mma_s8(A0m, a0h, bl0); mma_s8(A0m, a0l, bh0);
                mma_s8(B0h, a0h, bh1); mma_s8(B0m, a0h, bl1); mma_s8(B0m, a0l, bh1);
            }
        }

        // combine digit passes and dump partials (same slot map as fp16 version)
        {
            float4 f;
            f = make_float4(256.f*A0h[0]+A0m[0], 256.f*A0h[1]+A0m[1], 256.f*A0h[2]+A0m[2], 256.f*A0h[3]+A0m[3]);
            s_red4[((wid * 2 + 0) * 2 + 0) * 32 + lane] = f;
            f = make_float4(256.f*B0h[0]+B0m[0], 256.f*B0h[1]+B0m[1], 256.f*B0h[2]+B0m[2], 256.f*B0h[3]+B0m[3]);
            s_red4[((wid * 2 + 0) * 2 + 1) * 32 + lane] = f;
            f = make_float4(256.f*A1h[0]+A1m[0], 256.f*A1h[1]+A1m[1], 256.f*A1h[2]+A1m[2], 256.f*A1h[3]+A1m[3]);
            s_red4[((wid * 2 + 1) * 2 + 0) * 32 + lane] = f;
            f = make_float4(256.f*B1h[0]+B1m[0], 256.f*B1h[1]+B1m[1], 256.f*B1h[2]+B1m[2], 256.f*B1h[3]+B1m[3]);
            s_red4[((wid * 2 + 1) * 2 + 1) * 32 + lane] = f;
        }
        __syncthreads();

        if (tid < 256) {
            float sums[4];
#pragma unroll
            for (int gate = 0; gate < 4; gate++) {
                const int mt = gate >> 1;
                const int reg = 2 * (gate & 1) + cbit;
                float s = 0.f;
#pragma unroll
                for (int sq = 0; sq < 8; sq++) {
                    const int w = nh_ * 8 + sq;
                    s += s_red[(((w * 2 + mt) * 2 + ntl_) * 32 + ln) * 4 + reg];
                }
                sums[gate] = s;
            }
            sums[0] *= wsc0; sums[1] *= wsc1; sums[2] *= wsc2; sums[3] *= wsc3;
            if (p < TT) {
                float gz, gh; unpack2(gxv, gz, gh);
                float z  = 1.f / (1.f + expf(-(sums[0] + gz + bz0e)));
                float th = tanhf(sums[1] + gh);
                float hn = (1.f - z) * h0_old + z * th;
                h0_old = hn;
                s_h0[e_j * 33 + e_b] = hn;
            }
            if (p >= 1) {
                float z  = 1.f / (1.f + expf(-(sums[2] + bz1e)));
                float th = tanhf(sums[3]);
                float hn = (1.f - z) * h1_old + z * th;
                h1_old = hn;
                s_h1[e_j * 33 + e_b] = hn;
            }
        }
        __syncthreads();

        // repack staged h into int8 frag image of buffer p+1 (1 word per thread)
        if (tid < 256) {
            const int b = tid & 31, kq = (tid >> 5) & 1, digit = (tid >> 6) & 1, img = tid >> 7;
            const bool doit = img ? (p >= 1 && p < TT) : (p < TT);
            if (doit) {
                const int kg = (img ? 1024 : 0) + c * 8 + kq * 4;
                const int kstep = kg >> 5, koff = kg & 31;
                const int r = (koff >> 4) & 1, tg2 = (koff >> 2) & 3;
                const int lane2 = 4 * (b & 7) + tg2, nt = b >> 3;
                const float* sh = img ? s_h1 : s_h0;
                unsigned wd = 0;
#pragma unroll
                for (int byte = 0; byte < 4; byte++) {
                    float v = sh[(kq * 4 + byte) * 33 + b];
                    int hi, lo; quant15(v, QS, hi, lo);
                    int sel = digit ? lo : hi;
                    wd |= ((unsigned)(sel & 0xff)) << (8 * byte);
                }
                size_t word = (((size_t)kstep * 4 + nt) * 32 + lane2) * 4 + digit * 2 + r;
                stcg32(g_bimgN + (size_t)(p + 1) * 32768 + word, wd);
            }
        }
        if (p < TT) gridbar(p + 1, c, tid);
    }

    // ---- final output row + h_n tail ----
    if (tid < 256) {
        int b = tid >> 3, j = tid & 7;
        out[((size_t)b * TT + (TT - 1)) * HH + c * 8 + j] = s_h1[j * 33 + b];
        const size_t base = (size_t)BB * TT * HH;
        out[base + (size_t)e_b * HH + jg] = h0_old;                     // h0(T)
        out[base + (size_t)BB * HH + (size_t)e_b * HH + jg] = h1_old;   // h1(T)
    }
}

// ---------------- launcher ----------------
extern "C" void kernel_launch(void* const* d_in, const int* in_sizes, int n_in,
                              void* d_out, int out_size) {
    const float* x      = (const float*)d_in[0];
    const float* h0     = (const float*)d_in[1];
    const float* W_in0  = (const float*)d_in[2];
    const float* W_res0 = (const float*)d_in[3];
    const float* W_z0   = (const float*)d_in[4];
    const float* U_z0   = (const float*)d_in[5];
    const float* b_z0   = (const float*)d_in[6];
    const float* W_in1  = (const float*)d_in[7];
    const float* W_res1 = (const float*)d_in[8];
    const float* W_z1   = (const float*)d_in[9];
    const float* U_z1   = (const float*)d_in[10];
    const float* b_z1   = (const float*)d_in[11];
    float* out = (float*)d_out;

    static int configured = 0;
    if (!configured) {
        cudaFuncSetAttribute(k_esgp, cudaFuncAttributeMaxDynamicSharedMemorySize, SMEM_BYTES);
        cudaFuncSetAttribute(k_gx, cudaFuncAttributeMaxDynamicSharedMemorySize, 49152);
        configured = 1;
    }

    // launch order keeps k_esgp in the ncu capture slot (4th)
    k_prep1<<<16384 + 1024 + 4096, 256>>>(x, W_z0, W_in0, U_z0, W_res0, W_z1, U_z1, W_in1, W_res1);
    k_gx<<<dim3(128, 128), 256, 49152>>>(x);
    k_prep2<<<12288 + 256, 256>>>(U_z0, W_res0, W_z1, U_z1, W_in1, W_res1, h0);
    k_esgp<<<GCTA, NT, SMEM_BYTES>>>(b_z0, b_z1, h0, out);
}

// round 13
// speedup vs baseline: 2.1276x; 2.1276x over previous
#include <cuda_runtime.h>
#include <cuda_fp16.h>
#include <math.h>
#include <stdint.h>
#include <string.h>

#define BB 32
#define TT 1024
#define II 512
#define HH 1024
#define GCTA 128
#define NT 512

typedef unsigned long long ull;

// ---------------- device global scratch ----------------
__device__ float  g_xT[(size_t)TT * II * BB];          // x transposed [t][i][b]
__device__ float4 g_wpx[(size_t)128 * 256 * 8];        // x-proj weights pair-packed
__device__ ull    g_gx[(size_t)TT * HH * BB];          // precomputed x-gates (z,h~) fp32 pair
__device__ unsigned g_wfrag[(size_t)GCTA * 24576];     // per-CTA fp16 weight frag images (12MB)
__device__ unsigned g_bimgN[(size_t)(TT + 1) * 65536]; // per-step act frag images (268MB)
__device__ volatile int g_flags[GCTA];

// ---------------- helpers ----------------
__device__ __forceinline__ ull dup2(float w) {
    ull r; asm("mov.b64 %0, {%1, %1};" : "=l"(r) : "f"(w)); return r;
}
__device__ __forceinline__ void ffma2(ull &d, ull a, ull b) {
    asm("fma.rn.f32x2 %0, %1, %2, %0;" : "+l"(d) : "l"(a), "l"(b));
}
__device__ __forceinline__ ull add2(ull a, ull b) {
    ull d; asm("add.rn.f32x2 %0, %1, %2;" : "=l"(d) : "l"(a), "l"(b)); return d;
}
__device__ __forceinline__ void unpack2(ull v, float &lo, float &hi) {
    asm("mov.b64 {%0, %1}, %2;" : "=f"(lo), "=f"(hi) : "l"(v));
}
__device__ __forceinline__ void stcg32(unsigned* p, unsigned v) {
    asm volatile("st.global.cg.u32 [%0], %1;" :: "l"(p), "r"(v) : "memory");
}
__device__ __forceinline__ void mma16816h(float* d, uint4 a, uint2 b) {
    asm volatile(
        "mma.sync.aligned.m16n8k16.row.col.f32.f16.f16.f32 "
        "{%0,%1,%2,%3}, {%4,%5,%6,%7}, {%8,%9}, {%0,%1,%2,%3};"
        : "+f"(d[0]), "+f"(d[1]), "+f"(d[2]), "+f"(d[3])
        : "r"(a.x), "r"(a.y), "r"(a.z), "r"(a.w), "r"(b.x), "r"(b.y));
}
// fast gate math (MUFU.EX2 based): error ~1e-6, negligible vs fp16 path error
__device__ __forceinline__ float fsig(float x) {
    return 1.f / (1.f + __expf(-x));
}
__device__ __forceinline__ float ftanh(float x) {
    float xc = fminf(fmaxf(x, -40.f), 40.f);
    float e = __expf(2.f * xc);
    return __fdividef(e - 1.f, e + 1.f);
}

// ---------------- flag-based grid barrier ----------------
__device__ __forceinline__ void gridbar(int target, int cta, int tid) {
    __syncthreads();
    if (tid == 0) { __threadfence(); g_flags[cta] = target; }
    if (tid < 32) {
        bool done = false;
        while (!done) {
            int ok = 1;
#pragma unroll
            for (int q = 0; q < GCTA / 32; q++)
                if (g_flags[tid + 32 * q] < target) ok = 0;
            done = __all_sync(0xffffffffu, ok);
        }
        __threadfence();
    }
    __syncthreads();
}

// ---------------- prep1: transpose x  +  pack x-proj weights ----------------
__global__ void k_prep1(const float* __restrict__ x,
                        const float* __restrict__ W_z0, const float* __restrict__ W_in0) {
    int bid = blockIdx.x;
    if (bid < 16384) {
        __shared__ float tile[32][33];
        int t = bid >> 4;
        int i0 = (bid & 15) * 32;
        int lane = threadIdx.x & 31, row = threadIdx.x >> 5;
#pragma unroll
        for (int r = 0; r < 4; r++) {
            int b = row * 4 + r;
            tile[b][lane] = x[((size_t)b * TT + t) * II + i0 + lane];
        }
        __syncthreads();
#pragma unroll
        for (int r = 0; r < 4; r++) {
            int ii = row * 4 + r;
            g_xT[((size_t)t * II + i0 + ii) * BB + lane] = tile[lane][ii];
        }
    } else {
        int idx = (bid - 16384) * 256 + threadIdx.x;
        if (idx < 128 * 256 * 8) {
            int j  = idx & 7;
            int r  = idx >> 3;
            int k2 = r & 255;
            int jb = r >> 8;
            size_t row = (size_t)(jb * 8 + j) * II;
            float4 v;
            v.x = W_z0[row + 2 * k2];     v.y = W_in0[row + 2 * k2];
            v.z = W_z0[row + 2 * k2 + 1]; v.w = W_in0[row + 2 * k2 + 1];
            g_wpx[idx] = v;
        }
    }
}

// ---------------- gx: precompute x-gates (fp32 exact) ----------------
__global__ void __launch_bounds__(256, 1) k_gx(const float* __restrict__ dummy) {
    extern __shared__ ull sm_gx[];
    ulonglong2* sw = (ulonglong2*)sm_gx;
    ull*        pr = sm_gx + 4096;

    const int jb = blockIdx.x;
    const int tb = blockIdx.y;
    const int tid = threadIdx.x;
    const int w = tid >> 5;
    const int lane = tid & 31;

    const float4* src = g_wpx + (size_t)jb * 2048;
#pragma unroll
    for (int u = 0; u < 8; u++) ((float4*)sw)[tid + u * 256] = src[tid + u * 256];
    __syncthreads();

    for (int tt = 0; tt < 8; tt++) {
        const int t = tb * 8 + tt;
        ull acc[8];
#pragma unroll
        for (int j = 0; j < 8; j++) acc[j] = 0;
        const float* xp = g_xT + (size_t)t * II * BB;
#pragma unroll 4
        for (int u = 0; u < 32; u++) {
            const int k2 = w * 32 + u;
            ull A0 = dup2(__ldg(xp + (2 * k2) * BB + lane));
            ull A1 = dup2(__ldg(xp + (2 * k2 + 1) * BB + lane));
#pragma unroll
            for (int j = 0; j < 8; j++) {
                ulonglong2 wv = sw[k2 * 8 + j];
                ffma2(acc[j], wv.x, A0);
                ffma2(acc[j], wv.y, A1);
            }
        }
#pragma unroll
        for (int j = 0; j < 8; j++) pr[w * 256 + j * 32 + lane] = acc[j];
        __syncthreads();
        if (tid < 256) {
            const int e_j = tid >> 5;
            const int e_b = tid & 31;
            ull s = pr[e_j * 32 + e_b];
#pragma unroll
            for (int ww = 1; ww < 8; ww++) s = add2(s, pr[ww * 256 + e_j * 32 + e_b]);
            g_gx[((size_t)t * HH + jb * 8 + e_j) * BB + e_b] = s;
        }
        __syncthreads();
    }
}

// ---------------- prep2: pack fp16 weight frag images + seed act images ---------
__global__ void k_prep2(const float* __restrict__ U_z0, const float* __restrict__ W_res0,
                        const float* __restrict__ W_z1, const float* __restrict__ U_z1,
                        const float* __restrict__ W_in1, const float* __restrict__ W_res1,
                        const float* __restrict__ h0)
{
    int bid = blockIdx.x;
    if (bid < 12288) {
        size_t idx = (size_t)bid * 256 + threadIdx.x;
        int cta = (int)(idx / 24576);
        int rem = (int)(idx % 24576);
        int mt, rsub;
        if (rem < 8192) { mt = 0; rsub = rem; }
        else { mt = 1; rsub = rem - 8192; }
        int ksg = rsub >> 7;
        int lane = (rsub >> 2) & 31;
        int w = rsub & 3;
        int g = lane >> 2, tg = lane & 3;
        int row = 8 * (w & 1) + g;
        int kk = ksg * 16 + 2 * tg + 8 * (w >> 1);
        int j = cta * 8 + (row & 7);
        unsigned word = 0;
#pragma unroll
        for (int h = 0; h < 2; h++) {
            int k = kk + h;
            float v;
            if (mt == 0) {
                v = (row < 8) ? U_z0[(size_t)j * HH + k] : W_res0[(size_t)j * HH + k];
            } else {
                if (row < 8) v = (k < 1024) ? W_z1[(size_t)j * HH + k] : U_z1[(size_t)j * HH + k - 1024];
                else         v = (k < 1024) ? W_in1[(size_t)j * HH + k] : W_res1[(size_t)j * HH + k - 1024];
            }
            __half hv = __float2half(v);
            unsigned short us; memcpy(&us, &hv, 2);
            word |= ((unsigned)us) << (16 * h);
        }
        g_wfrag[idx] = word;
    } else {
        if (bid == 12288 && threadIdx.x < GCTA) g_flags[threadIdx.x] = 0;
        int idx = (bid - 12288) * 256 + threadIdx.x;
        if (idx < 2048 * 32) {
            int k = idx >> 5, b = idx & 31;
            float v = (k < 1024) ? h0[(size_t)(0 * BB + b) * HH + k]
                                 : h0[(size_t)(1 * BB + b) * HH + (k - 1024)];
            __half hi = __float2half(v);
            __half lo = __float2half(v - __half2float(hi));
            unsigned short uhi, ulo; memcpy(&uhi, &hi, 2); memcpy(&ulo, &lo, 2);
            int ks = k >> 4, tg = (k >> 1) & 3, r = (k >> 3) & 1, h = k & 1;
            int nt = b >> 3, g = b & 7, lane = 4 * g + tg;
            unsigned short* hw = (unsigned short*)g_bimgN;
            size_t inner = (((size_t)ks * 4 + nt) * 32 + lane) * 8 + r * 2 + h;
            hw[inner] = uhi; hw[inner + 4] = ulo;
            if (k >= 1024) {   // buffer 1 needs h1(0) half
                hw[131072 + inner] = uhi; hw[131072 + inner + 4] = ulo;
            }
        }
    }
}

// ---------------- main persistent kernel ----------------
// SMEM words: [weights 24576][s_red 8192][s_h0 264][s_h1 264]
#define SMEM_BYTES 133184
__global__ void __launch_bounds__(NT, 1) k_esgp(
    const float* __restrict__ b_z0, const float* __restrict__ b_z1,
    const float* __restrict__ h0in, float* __restrict__ out)
{
    extern __shared__ unsigned smw[];
    const int tid = threadIdx.x, wid = tid >> 5, lane = tid & 31, c = blockIdx.x;

    // preload fp16 weight fragment images (96KB)
    {
        const uint4* src = (const uint4*)(g_wfrag + (size_t)c * 24576);
        uint4* dst = (uint4*)smw;
        for (int i = tid; i < 6144; i += NT) dst[i] = src[i];
    }
    float*  s_red  = (float*)(smw + 24576);          // 8192 floats
    float4* s_red4 = (float4*)s_red;
    float*  s_h0   = (float*)(smw + 32768);          // 264 floats
    float*  s_h1   = s_h0 + 264;                     // 264 floats
    __syncthreads();

    // warp role: 8 ksg-slices x 2 nt-halves; each warp covers BOTH M-tiles
    const int ss = wid & 7, nh = wid >> 3;
    const int nt0 = nh * 2, nt1 = nh * 2 + 1;
    const uint4* ws0 = (const uint4*)smw + 0    + lane;   // mt0 (2048 uint4)
    const uint4* ws1 = (const uint4*)smw + 2048 + lane;   // mt1 (4096 uint4)

    // epilogue identity (tid<256): thread owns (e_j, e_b)
    const int e_j = wid, e_b = lane;
    const int jg = c * 8 + (e_j & 7);
    float bz0e = 0.f, bz1e = 0.f, h0_old = 0.f, h1_old = 0.f;
    if (tid < 256) {
        bz0e = b_z0[jg]; bz1e = b_z1[jg];
        h0_old = h0in[(size_t)(0 * BB + e_b) * HH + jg];
        h1_old = h0in[(size_t)(1 * BB + e_b) * HH + jg];
    }
    // epilogue gather constants
    const int nh_ = e_b >> 4, ntl_ = (e_b >> 3) & 1, col8 = e_b & 7;
    const int tg_ = col8 >> 1, cbit = col8 & 1;
    const int ln = 4 * (e_j & 7) + tg_;

    for (int p = 0; p <= TT; p++) {
        // deferred output write for step p-2 (s_h1 = h1(p-1), stable during MMA)
        if (p >= 2 && tid < 256) {
            int b = tid >> 3, j = tid & 7;
            out[((size_t)b * TT + (p - 2)) * HH + c * 8 + j] = s_h1[j * 33 + b];
        }

        float d0a[4] = {0,0,0,0}, d0b[4] = {0,0,0,0};
        float d1a[4] = {0,0,0,0}, d1b[4] = {0,0,0,0};
        float d1c[4] = {0,0,0,0}, d1d[4] = {0,0,0,0};
        const uint4* bi4 = (const uint4*)g_bimgN + (size_t)p * 16384 + lane;

        ull gxv = 0;
        if (tid < 256 && p < TT) gxv = __ldg(&g_gx[((size_t)p * HH + jg) * BB + e_b]);

        // ---- i = 0..7: ksg < 64, both M-tiles; blocked loads (MLP=8) ----
#pragma unroll
        for (int blk = 0; blk < 2; blk++) {
            uint4 bb0[4], bb1[4];
#pragma unroll
            for (int u = 0; u < 4; u++) {
                const int ksg = ss + 8 * (blk * 4 + u);
                bb0[u] = __ldg(bi4 + (ksg * 4 + nt0) * 32);
                bb1[u] = __ldg(bi4 + (ksg * 4 + nt1) * 32);
            }
#pragma unroll
            for (int u = 0; u < 4; u++) {
                const int ksg = ss + 8 * (blk * 4 + u);
                uint2 bh0 = make_uint2(bb0[u].x, bb0[u].y), bl0 = make_uint2(bb0[u].z, bb0[u].w);
                uint2 bh1 = make_uint2(bb1[u].x, bb1[u].y), bl1 = make_uint2(bb1[u].z, bb1[u].w);
                uint4 a1 = ws1[ksg * 32];
                mma16816h(d1a, a1, bh0); mma16816h(d1b, a1, bh1);
                mma16816h(d1a, a1, bl0); mma16816h(d1b, a1, bl1);
                uint4 a0 = ws0[ksg * 32];
                mma16816h(d0a, a0, bh0); mma16816h(d0b, a0, bh1);
                mma16816h(d0a, a0, bl0); mma16816h(d0b, a0, bl1);
            }
        }
        // ---- i = 8..15: ksg >= 64, M-tile 1 only; separate accumulators ----
#pragma unroll
        for (int blk = 2; blk < 4; blk++) {
            uint4 bb0[4], bb1[4];
#pragma unroll
            for (int u = 0; u < 4; u++) {
                const int ksg = ss + 8 * (blk * 4 + u);
                bb0[u] = __ldg(bi4 + (ksg * 4 + nt0) * 32);
                bb1[u] = __ldg(bi4 + (ksg * 4 + nt1) * 32);
            }
#pragma unroll
            for (int u = 0; u < 4; u++) {
                const int ksg = ss + 8 * (blk * 4 + u);
                uint2 bh0 = make_uint2(bb0[u].x, bb0[u].y), bl0 = make_uint2(bb0[u].z, bb0[u].w);
                uint2 bh1 = make_uint2(bb1[u].x, bb1[u].y), bl1 = make_uint2(bb1[u].z, bb1[u].w);
                uint4 a1 = ws1[ksg * 32];
                mma16816h(d1c, a1, bh0); mma16816h(d1d, a1, bh1);
                mma16816h(d1c, a1, bl0); mma16816h(d1d, a1, bl1);
            }
        }

        // ---- dump partials: slot q = ((wid*2 + mt)*2 + ntl), 32 float4 per slot ----
        s_red4[((wid * 2 + 0) * 2 + 0) * 32 + lane] = make_float4(d0a[0], d0a[1], d0a[2], d0a[3]);
        s_red4[((wid * 2 + 0) * 2 + 1) * 32 + lane] = make_float4(d0b[0], d0b[1], d0b[2], d0b[3]);
        s_red4[((wid * 2 + 1) * 2 + 0) * 32 + lane] =
            make_float4(d1a[0] + d1c[0], d1a[1] + d1c[1], d1a[2] + d1c[2], d1a[3] + d1c[3]);
        s_red4[((wid * 2 + 1) * 2 + 1) * 32 + lane] =
            make_float4(d1b[0] + d1d[0], d1b[1] + d1d[1], d1b[2] + d1d[2], d1b[3] + d1d[3]);
        __syncthreads();

        if (tid < 256) {
            float sums[4];
#pragma unroll
            for (int gate = 0; gate < 4; gate++) {
                const int mt = gate >> 1;
                const int reg = 2 * (gate & 1) + cbit;
                float s = 0.f;
#pragma unroll
                for (int sq = 0; sq < 8; sq++) {
                    const int w = nh_ * 8 + sq;
                    s += s_red[(((w * 2 + mt) * 2 + ntl_) * 32 + ln) * 4 + reg];
                }
                sums[gate] = s;
            }
            if (p < TT) {
                float gz, gh; unpack2(gxv, gz, gh);
                float z  = fsig(sums[0] + gz + bz0e);
                float th = ftanh(sums[1] + gh);
                float hn = (1.f - z) * h0_old + z * th;
                h0_old = hn;
                s_h0[e_j * 33 + e_b] = hn;
            }
            if (p >= 1) {
                float z  = fsig(sums[2] + bz1e);
                float th = ftanh(sums[3]);
                float hn = (1.f - z) * h1_old + z * th;
                h1_old = hn;
                s_h1[e_j * 33 + e_b] = hn;
            }
        }
        __syncthreads();

        // repack staged h into frag image of buffer p+1 (fp16 hi/lo, coalesced stores)
        if (tid < 256) {
            const int img = tid >> 7, ntq = (tid >> 5) & 3, lq = tid & 31;
            const bool doit = img ? (p >= 1 && p < TT) : (p < TT);
            if (doit) {
                const int tg2 = lq & 3, g2 = lq >> 2, b2 = ntq * 8 + g2;
                const float* sh = img ? s_h1 : s_h0;
                float v0 = sh[(2 * tg2) * 33 + b2];
                float v1 = sh[(2 * tg2 + 1) * 33 + b2];
                __half h0h = __float2half(v0);
                __half h1h = __float2half(v1);
                __half l0h = __float2half(v0 - __half2float(h0h));
                __half l1h = __float2half(v1 - __half2float(h1h));
                unsigned short a0, a1, q0, q1;
                memcpy(&a0, &h0h, 2); memcpy(&a1, &h1h, 2);
                memcpy(&q0, &l0h, 2); memcpy(&q1, &l1h, 2);
                unsigned whi = (unsigned)a0 | ((unsigned)a1 << 16);
                unsigned wlo = (unsigned)q0 | ((unsigned)q1 << 16);
                const int ksq = (img ? 64 : 0) + (c >> 1);
                const int r = c & 1;
                unsigned* wp = g_bimgN + (size_t)(p + 1) * 65536
                             + ((size_t)(ksq * 4 + ntq) * 32 + lq) * 4;
                stcg32(wp + r, whi);
                stcg32(wp + 2 + r, wlo);
            }
        }
        if (p < TT) gridbar(p + 1, c, tid);
    }

    // ---- final output row + h_n tail ----
    if (tid < 256) {
        int b = tid >> 3, j = tid & 7;
        out[((size_t)b * TT + (TT - 1)) * HH + c * 8 + j] = s_h1[j * 33 + b];
        const size_t base = (size_t)BB * TT * HH;
        out[base + (size_t)e_b * HH + jg] = h0_old;                     // h0(T)
        out[base + (size_t)BB * HH + (size_t)e_b * HH + jg] = h1_old;   // h1(T)
    }
}

// ---------------- launcher ----------------
extern "C" void kernel_launch(void* const* d_in, const int* in_sizes, int n_in,
                              void* d_out, int out_size) {
    const float* x      = (const float*)d_in[0];
    const float* h0     = (const float*)d_in[1];
    const float* W_in0  = (const float*)d_in[2];
    const float* W_res0 = (const float*)d_in[3];
    const float* W_z0   = (const float*)d_in[4];
    const float* U_z0   = (const float*)d_in[5];
    const float* b_z0   = (const float*)d_in[6];
    const float* W_in1  = (const float*)d_in[7];
    const float* W_res1 = (const float*)d_in[8];
    const float* W_z1   = (const float*)d_in[9];
    const float* U_z1   = (const float*)d_in[10];
    const float* b_z1   = (const float*)d_in[11];
    float* out = (float*)d_out;

    static int configured = 0;
    if (!configured) {
        cudaFuncSetAttribute(k_esgp, cudaFuncAttributeMaxDynamicSharedMemorySize, SMEM_BYTES);
        cudaFuncSetAttribute(k_gx, cudaFuncAttributeMaxDynamicSharedMemorySize, 49152);
        configured = 1;
    }

    // launch order keeps k_esgp in the ncu capture slot (4th)
    k_prep1<<<16384 + 1024, 256>>>(x, W_z0, W_in0);
    k_gx<<<dim3(128, 128), 256, 49152>>>(x);
    k_prep2<<<12288 + 256, 256>>>(U_z0, W_res0, W_z1, U_z1, W_in1, W_res1, h0);
    k_esgp<<<GCTA, NT, SMEM_BYTES>>>(b_z0, b_z1, h0, out);
}